// round 15
// baseline (speedup 1.0000x reference)
#include <cuda_runtime.h>
#include <cuda_bf16.h>
#include <cstdint>

#define BATCH  16384
#define DIM    128
#define NEDGES 500000
#define EPSL   1e-6f
#define PITCH  136   // bf16 elems per smem row (272 B = 17*16B) -> ldmatrix conflict-free
#define NTILE  128
#define NT     (NTILE * (NTILE + 1) / 2)   // 8256 triangular 128x128 tiles
#define L2E    1.4426950408889634f
#define L2E2   (1.4426950408889634f * 1.4426950408889634f)

// ---------------- device scratch ------------------------------------------------
__device__ __align__(16) float          g_ns[BATCH];
__device__ __align__(16) float          g_nq[BATCH];
__device__ __align__(16) float          g_bps[BATCH];
__device__ __align__(16) float          g_bp[BATCH];
__device__ __nv_bfloat16  g_psh[BATCH * DIM];
__device__ __nv_bfloat16  g_pph[BATCH * DIM];
__device__ double         g_acc[2];             // [0]=link, [1]=non_link
__device__ unsigned int   g_done;

// ---------------- gather (+ zero accumulators) ----------------------------------
__global__ void gather_kernel(const int* __restrict__ nodes_p_star,
                              const int* __restrict__ nodes_p,
                              const float* __restrict__ beta_p,
                              const float* __restrict__ beta_p_star,
                              const float* __restrict__ p,
                              const float* __restrict__ p_star) {
    if (blockIdx.x == 0 && threadIdx.x == 0) { g_acc[0] = 0.0; g_acc[1] = 0.0; }
    int gw   = (blockIdx.x * blockDim.x + threadIdx.x) >> 5;
    int lane = threadIdx.x & 31;
    if (gw >= 2 * BATCH) return;
    bool is_ps = (gw < BATCH);
    int r   = is_ps ? gw : gw - BATCH;
    int idx = is_ps ? nodes_p_star[r] : nodes_p[r];
    const float4* src = (const float4*)((is_ps ? p_star : p) + (size_t)idx * DIM);
    __nv_bfloat162* dsth = (__nv_bfloat162*)((is_ps ? g_psh : g_pph) + (size_t)r * DIM);
    float nrm = 0.f;
#pragma unroll
    for (int c = lane; c < DIM / 4; c += 32) {
        float4 v = src[c];
        nrm += v.x * v.x + v.y * v.y + v.z * v.z + v.w * v.w;
        dsth[2 * c]     = __floats2bfloat162_rn(v.x * L2E, v.y * L2E);
        dsth[2 * c + 1] = __floats2bfloat162_rn(v.z * L2E, v.w * L2E);
    }
#pragma unroll
    for (int o = 16; o; o >>= 1) nrm += __shfl_xor_sync(0xffffffffu, nrm, o);
    if (lane == 0) {
        if (is_ps) { g_ns[r] = nrm * L2E2; g_bps[r] = beta_p_star[idx] * L2E; }
        else       { g_nq[r] = nrm * L2E2; g_bp[r]  = beta_p[idx] * L2E; }
    }
}

// ---------------- helpers -------------------------------------------------------
__device__ __forceinline__ void ldsm_x4(uint32_t& r0, uint32_t& r1,
                                        uint32_t& r2, uint32_t& r3, const void* p) {
    uint32_t a = (uint32_t)__cvta_generic_to_shared(p);
    asm volatile("ldmatrix.sync.aligned.m8n8.x4.shared.b16 {%0,%1,%2,%3},[%4];"
                 : "=r"(r0), "=r"(r1), "=r"(r2), "=r"(r3) : "r"(a));
}
__device__ __forceinline__ void mma16816(float* c, const uint32_t* a, const uint32_t* b) {
    asm volatile(
        "mma.sync.aligned.m16n8k16.row.col.f32.bf16.bf16.f32 "
        "{%0,%1,%2,%3},{%4,%5,%6,%7},{%8,%9},{%0,%1,%2,%3};"
        : "+f"(c[0]), "+f"(c[1]), "+f"(c[2]), "+f"(c[3])
        : "r"(a[0]), "r"(a[1]), "r"(a[2]), "r"(a[3]), "r"(b[0]), "r"(b[1]));
}
__device__ __forceinline__ float fsqrt_ap(float x) {
    float r; asm("sqrt.approx.f32 %0, %1;" : "=f"(r) : "f"(x)); return r;
}
__device__ __forceinline__ float fex2_ap(float x) {
    float r; asm("ex2.approx.f32 %0, %1;" : "=f"(r) : "f"(x)); return r;
}
__device__ __forceinline__ void cp16(void* dst_smem, const void* src_gmem) {
    uint32_t d = (uint32_t)__cvta_generic_to_shared(dst_smem);
    asm volatile("cp.async.cg.shared.global [%0], [%1], 16;"
                 :: "r"(d), "l"(src_gmem) : "memory");
}

// ---------------- fused: async fill + link prologue + 128x128 tile --------------
__global__ void __launch_bounds__(512, 2) fused_kernel(
        const int* __restrict__ edges,
        const float* __restrict__ beta_p,
        const float* __restrict__ beta_p_star,
        const float* __restrict__ p,
        const float* __restrict__ p_star,
        float* __restrict__ out) {
    extern __shared__ __nv_bfloat16 sm[];
    __nv_bfloat16* As = sm;                           // [128][PITCH]
    __nv_bfloat16* Bs = sm + 128 * PITCH;             // [128][PITCH]
    float*         sPar = (float*)(sm + 2 * 128 * PITCH); // [512]: ns|bps|nq|bp
    __shared__ double sredl[16];
    __shared__ double sredn[16];

    int bid  = blockIdx.x;
    int tid  = threadIdx.x;
    int lane = tid & 31;
    int wid  = tid >> 5;

    // ===== tile decode (triangular: t = tq*(tq+1)/2 + ts, ts <= tq) =====
    int t  = bid;
    int tq = (int)((fsqrt_ap(8.f * (float)t + 1.f) - 1.f) * 0.5f);
    while ((tq + 1) * (tq + 2) / 2 <= t) tq++;
    while (tq * (tq + 1) / 2 > t) tq--;
    int ts = t - tq * (tq + 1) / 2;
    int s0 = ts * 128, q0 = tq * 128;
    bool masked = (ts == tq);

    // ===== async smem fill (tiles + epilogue params), in flight during link ====
    {
        int chunk = tid & 15;
        int rbase = tid >> 4;   // 0..31
#pragma unroll
        for (int i = 0; i < 4; i++) {
            int row = rbase + 32 * i;
            cp16(As + row * PITCH + chunk * 8,
                 g_psh + (size_t)(s0 + row) * DIM + chunk * 8);
            cp16(Bs + row * PITCH + chunk * 8,
                 g_pph + (size_t)(q0 + row) * DIM + chunk * 8);
        }
        if (tid < 128) {
            int a = tid >> 5;        // which array
            int c = tid & 31;        // 16B chunk
            const float* srcp = (a == 0) ? g_ns  + s0 :
                                (a == 1) ? g_bps + s0 :
                                (a == 2) ? g_nq  + q0 : g_bp + q0;
            cp16(sPar + a * 128 + c * 4, srcp + c * 4);
        }
        asm volatile("cp.async.commit_group;" ::: "memory");
    }

    // ===== link prologue: grid-strided edges, one warp per edge =====
    {
        float wacc = 0.f;
        for (int e = bid * 16 + wid; e < NEDGES; e += NT * 16) {
            int i0 = edges[e];
            int i1 = edges[NEDGES + e];
            float4 av = ((const float4*)(p      + (size_t)i0 * DIM))[lane];
            float4 bv = ((const float4*)(p_star + (size_t)i1 * DIM))[lane];
            float dx = av.x - bv.x + EPSL;
            float dy = av.y - bv.y + EPSL;
            float dz = av.z - bv.z + EPSL;
            float dw = av.w - bv.w + EPSL;
            float s = dx * dx + dy * dy + dz * dz + dw * dw;
#pragma unroll
            for (int o = 16; o; o >>= 1) s += __shfl_xor_sync(0xffffffffu, s, o);
            if (lane == 0)
                wacc += beta_p_star[i0] + beta_p[i1] - fsqrt_ap(s);
        }
        if (lane == 0) sredl[wid] = (double)wacc;
    }

    asm volatile("cp.async.wait_group 0;" ::: "memory");
    __syncthreads();

    if (tid == 0) {
        double tl = 0.0;
#pragma unroll
        for (int w = 0; w < 16; w++) tl += sredl[w];
        atomicAdd(&g_acc[0], tl);
    }

    // ===== MMA mainloop: 16 warps, warp -> 32x32 =====
    int m_base = (wid & 3) * 32;
    int n_base = (wid >> 2) * 32;

    float acc[2][4][4];
#pragma unroll
    for (int mi = 0; mi < 2; mi++)
#pragma unroll
        for (int nj = 0; nj < 4; nj++)
#pragma unroll
            for (int r = 0; r < 4; r++) acc[mi][nj][r] = 0.f;

    int a_row_off = lane & 15;
    int a_k_off   = 8 * (lane >> 4);
    int b_row_off = ((lane >> 4) << 3) + (lane & 7);
    int b_k_off   = ((lane >> 3) & 1) * 8;

#pragma unroll
    for (int k0 = 0; k0 < DIM; k0 += 16) {
        uint32_t a[2][4];
#pragma unroll
        for (int mi = 0; mi < 2; mi++) {
            const __nv_bfloat16* pa =
                As + (m_base + mi * 16 + a_row_off) * PITCH + k0 + a_k_off;
            ldsm_x4(a[mi][0], a[mi][1], a[mi][2], a[mi][3], pa);
        }
        uint32_t b[4][2];
#pragma unroll
        for (int pr = 0; pr < 2; pr++) {
            const __nv_bfloat16* pb =
                Bs + (n_base + pr * 16 + b_row_off) * PITCH + k0 + b_k_off;
            uint32_t r0, r1, r2, r3;
            ldsm_x4(r0, r1, r2, r3, pb);
            b[pr * 2][0] = r0; b[pr * 2][1] = r1;
            b[pr * 2 + 1][0] = r2; b[pr * 2 + 1][1] = r3;
        }
#pragma unroll
        for (int mi = 0; mi < 2; mi++)
#pragma unroll
            for (int nj = 0; nj < 4; nj++)
                mma16816(acc[mi][nj], a[mi], b[nj]);
    }

    // ===== fused epilogue (params from smem; ex2-folded approx MUFU) =====
    int g = lane >> 2, tt = lane & 3;
    float nsv[4], bpsv[4];
#pragma unroll
    for (int mi = 0; mi < 2; mi++) {
        int r = m_base + mi * 16 + g;
        nsv[2 * mi]      = sPar[r];            nsv[2 * mi + 1]  = sPar[r + 8];
        bpsv[2 * mi]     = sPar[128 + r];      bpsv[2 * mi + 1] = sPar[128 + r + 8];
    }
    float nqv[8], bpv[8];
#pragma unroll
    for (int nj = 0; nj < 4; nj++) {
        int c = n_base + nj * 8 + 2 * tt;
        nqv[2 * nj]     = sPar[256 + c];       nqv[2 * nj + 1] = sPar[256 + c + 1];
        bpv[2 * nj]     = sPar[384 + c];       bpv[2 * nj + 1] = sPar[384 + c + 1];
    }

    float lsum0 = 0.f, lsum1 = 0.f;
    if (!masked) {
#pragma unroll
        for (int mi = 0; mi < 2; mi++) {
#pragma unroll
            for (int nj = 0; nj < 4; nj++) {
#pragma unroll
                for (int rr = 0; rr < 4; rr++) {
                    float ns = nsv[2 * mi + (rr >> 1)];
                    float bs = bpsv[2 * mi + (rr >> 1)];
                    float nq = nqv[2 * nj + (rr & 1)];
                    float bq = bpv[2 * nj + (rr & 1)];
                    float sq = fmaxf(ns + fmaf(-2.f, acc[mi][nj][rr], nq), 0.f);
                    float e  = fex2_ap((bs + bq) - fsqrt_ap(sq));
                    if (rr & 1) lsum1 += e; else lsum0 += e;
                }
            }
        }
    } else {
#pragma unroll
        for (int mi = 0; mi < 2; mi++) {
            int rl0 = m_base + mi * 16 + g;
#pragma unroll
            for (int nj = 0; nj < 4; nj++) {
                int cl0 = n_base + nj * 8 + 2 * tt;
#pragma unroll
                for (int rr = 0; rr < 4; rr++) {
                    int rl = rl0 + (rr >> 1) * 8;
                    int cl = cl0 + (rr & 1);
                    float ns = nsv[2 * mi + (rr >> 1)];
                    float bs = bpsv[2 * mi + (rr >> 1)];
                    float nq = nqv[2 * nj + (rr & 1)];
                    float bq = bpv[2 * nj + (rr & 1)];
                    float sq = fmaxf(ns + fmaf(-2.f, acc[mi][nj][rr], nq), 0.f);
                    float e  = fex2_ap((bs + bq) - fsqrt_ap(sq));
                    if (cl > rl) { if (rr & 1) lsum1 += e; else lsum0 += e; }
                }
            }
        }
    }

    float lsum = lsum0 + lsum1;
#pragma unroll
    for (int o = 16; o; o >>= 1) lsum += __shfl_xor_sync(0xffffffffu, lsum, o);
    if (lane == 0) sredn[wid] = (double)lsum;
    __syncthreads();
    if (tid == 0) {
        double s = 0.0;
#pragma unroll
        for (int w = 0; w < 16; w++) s += sredn[w];
        atomicAdd(&g_acc[1], s);
        __threadfence();
        unsigned int done = atomicAdd(&g_done, 1u);
        if (done == NT - 1) {
            g_done = 0u;
            out[0] = (float)(g_acc[1] - g_acc[0]);
        }
    }
}

// ---------------- launch --------------------------------------------------------
extern "C" void kernel_launch(void* const* d_in, const int* in_sizes, int n_in,
                              void* d_out, int out_size) {
    const int*   edges        = (const int*)d_in[0];
    const int*   nodes_p_star = (const int*)d_in[1];
    const int*   nodes_p      = (const int*)d_in[2];
    const float* beta_p       = (const float*)d_in[3];
    const float* beta_p_star  = (const float*)d_in[4];
    const float* p            = (const float*)d_in[5];
    const float* p_star       = (const float*)d_in[6];
    float* out = (float*)d_out;

    static const size_t NL_SMEM =
        2 * 128 * PITCH * sizeof(__nv_bfloat16) + 512 * sizeof(float); // 71680 B
    cudaFuncSetAttribute(fused_kernel,
                         cudaFuncAttributeMaxDynamicSharedMemorySize, (int)NL_SMEM);

    gather_kernel<<<(2 * BATCH) / 8, 256>>>(nodes_p_star, nodes_p,
                                            beta_p, beta_p_star, p, p_star);

    fused_kernel<<<NT, 512, NL_SMEM>>>(edges, beta_p, beta_p_star, p, p_star, out);
}